// round 2
// baseline (speedup 1.0000x reference)
#include <cuda_runtime.h>
#include <math.h>

#define BATCH 2
#define SEQ   4096
#define DM    2048
#define DI    4096
#define NH    32
#define HD    128
#define DS    64
#define CONVD (DI + 2*DS)          /* 4224 */
#define DIP   (2*DI + 2*DS + NH)   /* 8352 */
#define OFF_DT (DI + CONVD)        /* 8320 */
#define CHUNK 256
#define NC    (SEQ/CHUNK)          /* 16 */
#define TOK   (BATCH*SEQ)          /* 8192 */

// ---------------- scratch (device globals; no allocation allowed) ----------------
__device__ float g_zxbcdt[(size_t)TOK*DIP];            // 274 MB
__device__ float g_dtsp[TOK*NH];
__device__ float g_dacs[BATCH*NH*NC*CHUNK];            // per-chunk cumsum of A*dt
__device__ float g_csum[BATCH*NH*NC];                  // chunk totals
__device__ float g_X[(size_t)BATCH*NC*NH*CHUNK*HD];    // x*dt, tiled   134 MB
__device__ float g_Bm[BATCH*NC*CHUNK*DS];
__device__ float g_Cm[BATCH*NC*CHUNK*DS];
__device__ float g_G[BATCH*NC*CHUNK*CHUNK];            // C @ B^T per (b,c)
__device__ float g_states[(size_t)BATCH*NC*NH*HD*DS];
__device__ float g_inter[(size_t)BATCH*NC*NH*HD*DS];
__device__ float g_y[(size_t)TOK*DI];                  // 134 MB
__device__ float g_yn[(size_t)TOK*DI];                 // 134 MB

// ---------------- K1/K9: SGEMM  C[M,N] = A[M,K] @ B[N,K]^T + bias[N] ----------------
// M multiple of 128, K multiple of 16. N guarded. 128x128x16 tile, 8x8/thread.
__global__ __launch_bounds__(256) void sgemm_nt(
    const float* __restrict__ A, const float* __restrict__ B,
    const float* __restrict__ bias, float* __restrict__ C,
    int M, int N, int K)
{
    __shared__ __align__(16) float As[16][128];
    __shared__ __align__(16) float Bs[16][128];
    int tid = threadIdx.x;
    int tx = tid & 15, ty = tid >> 4;
    int m0 = blockIdx.y * 128, n0 = blockIdx.x * 128;

    float acc[8][8];
#pragma unroll
    for (int i = 0; i < 8; i++)
#pragma unroll
        for (int j = 0; j < 8; j++) acc[i][j] = 0.f;

    for (int k0 = 0; k0 < K; k0 += 16) {
#pragma unroll
        for (int u = 0; u < 2; u++) {
            int t = tid + u * 256;
            int r = t >> 2;
            int kk = (t & 3) << 2;
            float4 va = *(const float4*)&A[(size_t)(m0 + r) * K + k0 + kk];
            As[kk + 0][r] = va.x; As[kk + 1][r] = va.y;
            As[kk + 2][r] = va.z; As[kk + 3][r] = va.w;
            float4 vb = make_float4(0.f, 0.f, 0.f, 0.f);
            if (n0 + r < N) vb = *(const float4*)&B[(size_t)(n0 + r) * K + k0 + kk];
            Bs[kk + 0][r] = vb.x; Bs[kk + 1][r] = vb.y;
            Bs[kk + 2][r] = vb.z; Bs[kk + 3][r] = vb.w;
        }
        __syncthreads();
#pragma unroll
        for (int kk = 0; kk < 16; kk++) {
            float a[8], b[8];
            *(float4*)&a[0] = *(float4*)&As[kk][ty * 8];
            *(float4*)&a[4] = *(float4*)&As[kk][ty * 8 + 4];
            *(float4*)&b[0] = *(float4*)&Bs[kk][tx * 8];
            *(float4*)&b[4] = *(float4*)&Bs[kk][tx * 8 + 4];
#pragma unroll
            for (int i = 0; i < 8; i++)
#pragma unroll
                for (int j = 0; j < 8; j++)
                    acc[i][j] = fmaf(a[i], b[j], acc[i][j]);
        }
        __syncthreads();
    }

#pragma unroll
    for (int i = 0; i < 8; i++) {
        int m = m0 + ty * 8 + i;
#pragma unroll
        for (int j = 0; j < 8; j += 4) {
            int n = n0 + tx * 8 + j;
            if (n + 3 < N) {
                float4 v;
                v.x = acc[i][j + 0] + bias[n + 0];
                v.y = acc[i][j + 1] + bias[n + 1];
                v.z = acc[i][j + 2] + bias[n + 2];
                v.w = acc[i][j + 3] + bias[n + 3];
                *(float4*)&C[(size_t)m * N + n] = v;
            } else {
                for (int q = 0; q < 4; q++)
                    if (n + q < N) C[(size_t)m * N + n + q] = acc[i][j + q] + bias[n + q];
            }
        }
    }
}

// ---------------- K2: dt softplus + per-chunk inclusive cumsum of A*dt ----------------
__global__ __launch_bounds__(256) void dt_scan_kernel(
    const float* __restrict__ dt_bias, const float* __restrict__ A_log)
{
    int blk = blockIdx.x;            // (b*NH + h)*NC + c
    int c = blk % NC; int bh = blk / NC;
    int h = bh % NH;  int b = bh / NH;
    int t = threadIdx.x;
    int l = c * CHUNK + t;

    float x = g_zxbcdt[(size_t)(b * SEQ + l) * DIP + OFF_DT + h] + dt_bias[h];
    float sp = (x > 20.f) ? x : log1pf(expf(x));
    g_dtsp[(b * SEQ + l) * NH + h] = sp;
    float da = -expf(A_log[h]) * sp;

    __shared__ float s[CHUNK];
    s[t] = da;
    __syncthreads();
    for (int off = 1; off < CHUNK; off <<= 1) {
        float v = (t >= off) ? s[t - off] : 0.f;
        __syncthreads();
        s[t] += v;
        __syncthreads();
    }
    int base = ((b * NH + h) * NC + c) * CHUNK;
    g_dacs[base + t] = s[t];
    if (t == CHUNK - 1) g_csum[(b * NH + h) * NC + c] = s[t];
}

// ---------------- K3: causal depthwise conv4 + SiLU + scatter ----------------
__global__ __launch_bounds__(256) void conv_kernel(
    const float* __restrict__ conv_w, const float* __restrict__ conv_b)
{
    int tok = blockIdx.x;                       // 0..TOK-1
    int ch = blockIdx.y * 256 + threadIdx.x;
    if (ch >= CONVD) return;
    int b = tok / SEQ, l = tok % SEQ;

    const float* w = conv_w + ch * 4;
    float acc = conv_b[ch];
#pragma unroll
    for (int j = 0; j < 4; j++) {
        int ls = l - 3 + j;
        if (ls >= 0)
            acc += w[j] * g_zxbcdt[(size_t)(b * SEQ + ls) * DIP + DI + ch];
    }
    float v = acc / (1.f + __expf(-acc));       // silu

    int c = l / CHUNK, t = l % CHUNK;
    if (ch < DI) {
        int h = ch >> 7, p = ch & 127;
        float dt = g_dtsp[(b * SEQ + l) * NH + h];
        g_X[(size_t)(((b * NC + c) * NH + h) * CHUNK + t) * HD + p] = v * dt;
    } else if (ch < DI + DS) {
        g_Bm[((b * NC + c) * CHUNK + t) * DS + (ch - DI)] = v;
    } else {
        g_Cm[((b * NC + c) * CHUNK + t) * DS + (ch - DI - DS)] = v;
    }
}

// ---------------- K4: G[l,s] = sum_n C[l,n] B[s,n] per (b,c) ----------------
__global__ __launch_bounds__(256) void bc_gemm_kernel()
{
    int bc = blockIdx.y;                         // 0..31
    int tile = blockIdx.x;                       // 0..15
    int l0 = (tile >> 2) * 64, s0 = (tile & 3) * 64;
    __shared__ float Cs[64][65];
    __shared__ float Bs[64][65];
    int tid = threadIdx.x;
    const float* Cb = g_Cm + (size_t)bc * CHUNK * DS;
    const float* Bb = g_Bm + (size_t)bc * CHUNK * DS;

#pragma unroll
    for (int u = 0; u < 4; u++) {
        int e = tid + u * 256;                   // 1024 float4
        int r = e >> 4, cv = (e & 15) << 2;
        float4 vc = *(const float4*)&Cb[(l0 + r) * DS + cv];
        Cs[r][cv + 0] = vc.x; Cs[r][cv + 1] = vc.y; Cs[r][cv + 2] = vc.z; Cs[r][cv + 3] = vc.w;
        float4 vb = *(const float4*)&Bb[(s0 + r) * DS + cv];
        Bs[r][cv + 0] = vb.x; Bs[r][cv + 1] = vb.y; Bs[r][cv + 2] = vb.z; Bs[r][cv + 3] = vb.w;
    }
    __syncthreads();

    int sq = tid & 15, lq = tid >> 4;
    float acc[4][4];
#pragma unroll
    for (int i = 0; i < 4; i++)
#pragma unroll
        for (int j = 0; j < 4; j++) acc[i][j] = 0.f;

#pragma unroll 8
    for (int n = 0; n < 64; n++) {
        float a[4], bb[4];
#pragma unroll
        for (int i = 0; i < 4; i++) a[i] = Cs[lq * 4 + i][n];
#pragma unroll
        for (int j = 0; j < 4; j++) bb[j] = Bs[sq * 4 + j][n];
#pragma unroll
        for (int i = 0; i < 4; i++)
#pragma unroll
            for (int j = 0; j < 4; j++) acc[i][j] = fmaf(a[i], bb[j], acc[i][j]);
    }
    float* Gout = g_G + (size_t)bc * CHUNK * CHUNK;
#pragma unroll
    for (int i = 0; i < 4; i++) {
        float4 v = make_float4(acc[i][0], acc[i][1], acc[i][2], acc[i][3]);
        *(float4*)&Gout[(l0 + lq * 4 + i) * CHUNK + s0 + sq * 4] = v;
    }
}

// ---------------- K5: Y_diag = (G .* L) @ X per (b,c,h) ----------------
__global__ __launch_bounds__(512) void ydiag_kernel()
{
    int blk = blockIdx.x;                        // ((b*NC+c)*NH + h)
    int h = blk % NH; int bc = blk / NH;
    int c = bc % NC;  int b = bc / NC;

    __shared__ __align__(16) float Ms[16][256];
    __shared__ __align__(16) float Xs[16][128];
    __shared__ float acs[CHUNK];
    int tid = threadIdx.x;
    if (tid < 256) acs[tid] = g_dacs[((b * NH + h) * NC + c) * CHUNK + tid];
    __syncthreads();

    const float* Gb = g_G + (size_t)bc * CHUNK * CHUNK;
    const float* Xb = g_X + (size_t)blk * CHUNK * HD;

    float acc[8][8];
#pragma unroll
    for (int i = 0; i < 8; i++)
#pragma unroll
        for (int j = 0; j < 8; j++) acc[i][j] = 0.f;

    int tx = tid & 15, ty = tid >> 4;            // ty 0..31 (l), tx 0..15 (p)

    for (int s0 = 0; s0 < CHUNK; s0 += 16) {
        {   // X tile: 16 x 128, 512 float4, one per thread
            int r = tid >> 5, cv = (tid & 31) << 2;
            float4 v = *(const float4*)&Xb[(s0 + r) * HD + cv];
            *(float4*)&Xs[r][cv] = v;
        }
#pragma unroll
        for (int u = 0; u < 2; u++) {            // M tile: 256 x 16 transposed
            int e = tid * 2 + u;
            int r = e >> 2;                      // l
            int sv = (e & 3) << 2;               // s offset
            float4 g4 = *(const float4*)&Gb[r * CHUNK + s0 + sv];
            float al = acs[r];
            int sg = s0 + sv;
            Ms[sv + 0][r] = (sg + 0 <= r) ? g4.x * __expf(al - acs[sg + 0]) : 0.f;
            Ms[sv + 1][r] = (sg + 1 <= r) ? g4.y * __expf(al - acs[sg + 1]) : 0.f;
            Ms[sv + 2][r] = (sg + 2 <= r) ? g4.z * __expf(al - acs[sg + 2]) : 0.f;
            Ms[sv + 3][r] = (sg + 3 <= r) ? g4.w * __expf(al - acs[sg + 3]) : 0.f;
        }
        __syncthreads();
#pragma unroll
        for (int kk = 0; kk < 16; kk++) {
            float a[8], bb[8];
            *(float4*)&a[0] = *(float4*)&Ms[kk][ty * 8];
            *(float4*)&a[4] = *(float4*)&Ms[kk][ty * 8 + 4];
            *(float4*)&bb[0] = *(float4*)&Xs[kk][tx * 8];
            *(float4*)&bb[4] = *(float4*)&Xs[kk][tx * 8 + 4];
#pragma unroll
            for (int i = 0; i < 8; i++)
#pragma unroll
                for (int j = 0; j < 8; j++)
                    acc[i][j] = fmaf(a[i], bb[j], acc[i][j]);
        }
        __syncthreads();
    }

#pragma unroll
    for (int i = 0; i < 8; i++) {
        int l = ty * 8 + i;
        float* out = g_y + (size_t)(b * SEQ + c * CHUNK + l) * DI + h * HD;
#pragma unroll
        for (int j = 0; j < 8; j += 4) {
            float4 v = make_float4(acc[i][j], acc[i][j + 1], acc[i][j + 2], acc[i][j + 3]);
            *(float4*)&out[tx * 8 + j] = v;
        }
    }
}

// ---------------- K5b: local states[p,n] = sum_l X[l,p]*decay[l]*B[l,n] ----------------
__global__ __launch_bounds__(256) void states_kernel()
{
    int blk = blockIdx.x;
    int h = blk % NH; int bc = blk / NH;
    int c = bc % NC;  int b = bc / NC;

    __shared__ __align__(16) float Xs[32][128];
    __shared__ __align__(16) float Bs[32][64];
    __shared__ float ws[32];
    __shared__ float acs[CHUNK];
    int tid = threadIdx.x;
    if (tid < 256) acs[tid] = g_dacs[((b * NH + h) * NC + c) * CHUNK + tid];
    __syncthreads();
    float alast = acs[CHUNK - 1];

    const float* Xb = g_X + (size_t)blk * CHUNK * HD;
    const float* Bb = g_Bm + (size_t)bc * CHUNK * DS;

    int nq = tid & 7, pq = tid >> 3;             // p0 = pq*4 (0..124), n0 = nq*8
    float acc[4][8];
#pragma unroll
    for (int i = 0; i < 4; i++)
#pragma unroll
        for (int j = 0; j < 8; j++) acc[i][j] = 0.f;

    for (int l0 = 0; l0 < CHUNK; l0 += 32) {
#pragma unroll
        for (int u = 0; u < 4; u++) {            // X: 32x128 = 1024 float4
            int e = tid + u * 256;
            int r = e >> 5, cv = (e & 31) << 2;
            *(float4*)&Xs[r][cv] = *(const float4*)&Xb[(l0 + r) * HD + cv];
        }
#pragma unroll
        for (int u = 0; u < 2; u++) {            // B: 32x64 = 512 float4
            int e = tid + u * 256;
            int r = e >> 4, cv = (e & 15) << 2;
            *(float4*)&Bs[r][cv] = *(const float4*)&Bb[(l0 + r) * DS + cv];
        }
        if (tid < 32) ws[tid] = __expf(alast - acs[l0 + tid]);
        __syncthreads();
#pragma unroll
        for (int lt = 0; lt < 32; lt++) {
            float w = ws[lt];
            float a[4];
#pragma unroll
            for (int i = 0; i < 4; i++) a[i] = Xs[lt][pq * 4 + i] * w;
            float bb[8];
            *(float4*)&bb[0] = *(float4*)&Bs[lt][nq * 8];
            *(float4*)&bb[4] = *(float4*)&Bs[lt][nq * 8 + 4];
#pragma unroll
            for (int i = 0; i < 4; i++)
#pragma unroll
                for (int j = 0; j < 8; j++)
                    acc[i][j] = fmaf(a[i], bb[j], acc[i][j]);
        }
        __syncthreads();
    }
    float* So = g_states + (size_t)blk * HD * DS;
#pragma unroll
    for (int i = 0; i < 4; i++) {
#pragma unroll
        for (int j = 0; j < 8; j += 4) {
            float4 v = make_float4(acc[i][j], acc[i][j + 1], acc[i][j + 2], acc[i][j + 3]);
            *(float4*)&So[(pq * 4 + i) * DS + nq * 8 + j] = v;
        }
    }
}

// ---------------- K6: inter-chunk scan (16 sequential steps) ----------------
__global__ __launch_bounds__(256) void scan_kernel()
{
    int bh = blockIdx.x;                         // b*NH + h
    int b = bh / NH, h = bh % NH;
    int tid = threadIdx.x;
    float S[32];
#pragma unroll
    for (int k = 0; k < 32; k++) S[k] = 0.f;
    for (int c = 0; c < NC; c++) {
        float dec = __expf(g_csum[bh * NC + c]);
        size_t base = (size_t)((b * NC + c) * NH + h) * HD * DS;
#pragma unroll
        for (int k = 0; k < 32; k++) {
            int e = tid + k * 256;
            g_inter[base + e] = S[k];
            S[k] = S[k] * dec + g_states[base + e];
        }
    }
}

// ---------------- K7: Y_off + combine + silu(z) gate ----------------
__global__ __launch_bounds__(256) void yoff_kernel()
{
    int blk = blockIdx.x;
    int h = blk % NH; int bc = blk / NH;
    int c = bc % NC;  int b = bc / NC;

    __shared__ float Is[HD][DS + 1];             // inter, padded
    __shared__ float Cs[64][DS + 1];
    __shared__ float acs[CHUNK];
    int tid = threadIdx.x;
    if (tid < 256) acs[tid] = g_dacs[((b * NH + h) * NC + c) * CHUNK + tid];

    const float* Ib = g_inter + (size_t)blk * HD * DS;
#pragma unroll
    for (int u = 0; u < 8; u++) {                // 128x64 = 2048 float4
        int e = tid + u * 256;
        int r = e >> 4, cv = (e & 15) << 2;
        float4 v = *(const float4*)&Ib[r * DS + cv];
        Is[r][cv + 0] = v.x; Is[r][cv + 1] = v.y; Is[r][cv + 2] = v.z; Is[r][cv + 3] = v.w;
    }

    int tq = tid & 7, pq = tid >> 3;             // tq: t sub-lane, pq: p0 = pq*4
    const float* Cb = g_Cm + (size_t)bc * CHUNK * DS;

    for (int tg = 0; tg < 4; tg++) {
        __syncthreads();                          // protect Is (first iter) / Cs reuse
#pragma unroll
        for (int u = 0; u < 4; u++) {             // C tile 64x64 = 1024 float4
            int e = tid + u * 256;
            int r = e >> 4, cv = (e & 15) << 2;
            float4 v = *(const float4*)&Cb[(tg * 64 + r) * DS + cv];
            Cs[r][cv + 0] = v.x; Cs[r][cv + 1] = v.y; Cs[r][cv + 2] = v.z; Cs[r][cv + 3] = v.w;
        }
        __syncthreads();

        float acc[8][4];
#pragma unroll
        for (int k = 0; k < 8; k++)
#pragma unroll
            for (int i = 0; i < 4; i++) acc[k][i] = 0.f;

#pragma unroll 4
        for (int n = 0; n < DS; n++) {
            float iv[4];
#pragma unroll
            for (int i = 0; i < 4; i++) iv[i] = Is[pq * 4 + i][n];
#pragma unroll
            for (int k = 0; k < 8; k++) {
                float cv = Cs[k * 8 + tq][n];
#pragma unroll
                for (int i = 0; i < 4; i++)
                    acc[k][i] = fmaf(cv, iv[i], acc[k][i]);
            }
        }

#pragma unroll
        for (int k = 0; k < 8; k++) {
            int t = tg * 64 + k * 8 + tq;
            float ea = __expf(acs[t]);
            int gl = c * CHUNK + t;
            size_t yidx = (size_t)(b * SEQ + gl) * DI + h * HD + pq * 4;
            size_t zidx = (size_t)(b * SEQ + gl) * DIP + h * HD + pq * 4;
            float4 yd = *(float4*)&g_y[yidx];
            float4 z  = *(const float4*)&g_zxbcdt[zidx];
            float4 o;
            o.x = (yd.x + ea * acc[k][0]) * z.x / (1.f + __expf(-z.x));
            o.y = (yd.y + ea * acc[k][1]) * z.y / (1.f + __expf(-z.y));
            o.z = (yd.z + ea * acc[k][2]) * z.z / (1.f + __expf(-z.z));
            o.w = (yd.w + ea * acc[k][3]) * z.w / (1.f + __expf(-z.w));
            *(float4*)&g_y[yidx] = o;
        }
    }
}

// ---------------- K8: layernorm over 4096 ----------------
__global__ __launch_bounds__(256) void ln_kernel(
    const float* __restrict__ ln_w, const float* __restrict__ ln_b)
{
    int tok = blockIdx.x;
    const float* y = g_y + (size_t)tok * DI;
    float* o = g_yn + (size_t)tok * DI;
    int tid = threadIdx.x;

    float v[16];
    float s = 0.f, ss = 0.f;
#pragma unroll
    for (int u = 0; u < 4; u++) {
        float4 x = *(const float4*)&y[tid * 4 + u * 1024];
        v[u * 4 + 0] = x.x; v[u * 4 + 1] = x.y; v[u * 4 + 2] = x.z; v[u * 4 + 3] = x.w;
        s += x.x + x.y + x.z + x.w;
        ss += x.x * x.x + x.y * x.y + x.z * x.z + x.w * x.w;
    }
#pragma unroll
    for (int off = 16; off; off >>= 1) {
        s  += __shfl_xor_sync(0xFFFFFFFFu, s, off);
        ss += __shfl_xor_sync(0xFFFFFFFFu, ss, off);
    }
    __shared__ float rs[8], rss[8];
    int warp = tid >> 5, lane = tid & 31;
    if (lane == 0) { rs[warp] = s; rss[warp] = ss; }
    __syncthreads();
    s = 0.f; ss = 0.f;
#pragma unroll
    for (int w = 0; w < 8; w++) { s += rs[w]; ss += rss[w]; }
    float mu = s * (1.f / DI);
    float var = ss * (1.f / DI) - mu * mu;
    float rstd = rsqrtf(var + 1e-5f);
#pragma unroll
    for (int u = 0; u < 4; u++) {
        int idx = tid * 4 + u * 1024;
        float4 w4 = *(const float4*)&ln_w[idx];
        float4 b4 = *(const float4*)&ln_b[idx];
        float4 ov;
        ov.x = (v[u * 4 + 0] - mu) * rstd * w4.x + b4.x;
        ov.y = (v[u * 4 + 1] - mu) * rstd * w4.y + b4.y;
        ov.z = (v[u * 4 + 2] - mu) * rstd * w4.z + b4.z;
        ov.w = (v[u * 4 + 3] - mu) * rstd * w4.w + b4.w;
        *(float4*)&o[idx] = ov;
    }
}

// ---------------- launch ----------------
extern "C" void kernel_launch(void* const* d_in, const int* in_sizes, int n_in,
                              void* d_out, int out_size)
{
    const float* u          = (const float*)d_in[0];
    const float* in_proj_w  = (const float*)d_in[1];
    const float* in_proj_b  = (const float*)d_in[2];
    const float* conv_w     = (const float*)d_in[3];
    const float* conv_b     = (const float*)d_in[4];
    const float* dt_bias    = (const float*)d_in[5];
    const float* A_log      = (const float*)d_in[6];
    const float* ln_w       = (const float*)d_in[7];
    const float* ln_b       = (const float*)d_in[8];
    const float* out_proj_w = (const float*)d_in[9];
    const float* out_proj_b = (const float*)d_in[10];
    float* out = (float*)d_out;

    float* zx; cudaGetSymbolAddress((void**)&zx, g_zxbcdt);
    float* yn; cudaGetSymbolAddress((void**)&yn, g_yn);

    // K1: in_proj GEMM  (8192 x 8352 x 2048)
    sgemm_nt<<<dim3((DIP + 127) / 128, TOK / 128), 256>>>(
        u, in_proj_w, in_proj_b, zx, TOK, DIP, DM);
    // K2: dt softplus + per-chunk cumsum
    dt_scan_kernel<<<BATCH * NH * NC, CHUNK>>>(dt_bias, A_log);
    // K3: conv + silu + scatter
    conv_kernel<<<dim3(TOK, (CONVD + 255) / 256), 256>>>(conv_w, conv_b);
    // K4: G = C B^T per (b,c)
    bc_gemm_kernel<<<dim3(16, BATCH * NC), 256>>>();
    // K5: Y_diag
    ydiag_kernel<<<BATCH * NC * NH, 512>>>();
    // K5b: local chunk states
    states_kernel<<<BATCH * NC * NH, 256>>>();
    // K6: inter-chunk scan
    scan_kernel<<<BATCH * NH, 256>>>();
    // K7: Y_off + gate
    yoff_kernel<<<BATCH * NC * NH, 256>>>();
    // K8: layernorm
    ln_kernel<<<TOK, 256>>>(ln_w, ln_b);
    // K9: out_proj GEMM (8192 x 2048 x 4096)
    sgemm_nt<<<dim3(DM / 128, TOK / 128), 256>>>(
        yn, out_proj_w, out_proj_b, out, TOK, DM, DI);
}